// round 11
// baseline (speedup 1.0000x reference)
#include <cuda_runtime.h>
#include <math.h>

// Problem constants
#define O_DIM 32
#define I_DIM 32
#define K_DIM 13
#define N_DIM 4096
#define IK    (I_DIM * K_DIM)    // 416
#define WSIZE (O_DIM * IK)       // 13312 floats = 53 KB

#define THREADS 1024
#define BLOCKS  304              // 152 SMs * 2 resident blocks (all co-resident)

// Transposed x: xT[n][i] = x[i][n]  (4096 x 32 floats = 512 KB, L2-resident)
__device__ float xT[N_DIM * I_DIM];
// Grid-barrier epoch counter (monotonic across graph replays)
__device__ unsigned int g_bar;

__global__ void __launch_bounds__(THREADS, 2) plaq_kernel(
    const float* __restrict__ x,       // (I, N)
    const float* __restrict__ W,       // (O, I, K)
    const float* __restrict__ b,       // (O,)
    const float* __restrict__ mask,    // (N, O, I, K)
    const int*   __restrict__ shifts,  // (N, K)
    float*       __restrict__ out)     // (O, N)
{
    __shared__ __align__(8) float Wsh[WSIZE];
    __shared__ __align__(8) float gsh[2][IK];

    const int tid  = threadIdx.x;
    const int warp = tid >> 5;   // warp == o in the dot phase
    const int lane = tid & 31;
    const int bid  = blockIdx.x;

    // ---- Phase 1: in-kernel transpose (blocks 0..127, one 32x32 tile each).
    // Tile buffer aliases the head of Wsh (Wsh is written only after this phase).
    {
        float (*tile)[33] = (float(*)[33])Wsh;
        if (bid < N_DIM / 32) {
            const int n0t = bid * 32;
            tile[warp][lane] = x[warp * N_DIM + n0t + lane];
            __syncthreads();
            xT[(n0t + warp) * I_DIM + lane] = tile[lane][warp];
            __threadfence();               // publish xT before arriving
        }
        __syncthreads();                   // tile reads done before Wsh overwrite
    }

    // ---- Phase 2: load W into shared (overlaps other blocks' transpose work)
    #pragma unroll
    for (int e = tid; e < WSIZE; e += THREADS)
        Wsh[e] = W[e];
    __syncthreads();

    // ---- Phase 3: software grid barrier (replay-safe epoch arithmetic)
    if (tid == 0) {
        const unsigned old    = atomicAdd(&g_bar, 1u);
        const unsigned target = (old / BLOCKS + 1u) * BLOCKS;
        while (atomicAdd(&g_bar, 0u) < target)
            __nanosleep(64);
    }
    __syncthreads();

    const float bias = b[warp];
    const float e_const = 2.718281828459045f;
    const float scale = (2.0f + 2.0f * e_const) / (e_const - 1.0f);
    const float2* __restrict__ w2 = (const float2*)(Wsh + warp * IK);

    // ---- Phase 4: main loop, two n's per iteration (R9 structure, float2 dot)
    for (int n0 = 2 * bid; n0 < N_DIM; n0 += 2 * BLOCKS) {
        // Gather both n's: warp k (k<13) -> n0, warp 13+k -> n0+1.
        // One broadcast shift + one 128B xT row per warp; STS lane*13+k is
        // conflict-free (13 coprime with 32).
        if (warp < 2 * K_DIM) {
            const int which = (warp >= K_DIM) ? 1 : 0;
            const int k     = warp - which * K_DIM;
            const int s     = shifts[(n0 + which) * K_DIM + k];
            gsh[which][lane * K_DIM + k] = xT[s * I_DIM + lane];
        }
        __syncthreads();

        // Dot: 2x (6.5) coalesced LDG.64 per warp; 208 float2 per mask row
        const float2* __restrict__ m0 =
            (const float2*)(mask + ((size_t)n0 * O_DIM + warp) * IK);
        const float2* __restrict__ m1 = m0 + (O_DIM * IK / 2);
        const float2* __restrict__ g0 = (const float2*)gsh[0];
        const float2* __restrict__ g1 = (const float2*)gsh[1];

        float s0 = 0.0f, s1 = 0.0f;
        #pragma unroll
        for (int j = 0; j < 6; ++j) {
            const int c = j * 32 + lane;
            const float2 w  = w2[c];
            const float2 a0 = m0[c];
            const float2 ga = g0[c];
            s0 += a0.x * w.x * ga.x + a0.y * w.y * ga.y;
            const float2 a1 = m1[c];
            const float2 gb = g1[c];
            s1 += a1.x * w.x * gb.x + a1.y * w.y * gb.y;
        }
        if (lane < 16) {   // tail: float2 chunks 192..207
            const int c = 192 + lane;
            const float2 w  = w2[c];
            const float2 a0 = m0[c];
            const float2 ga = g0[c];
            s0 += a0.x * w.x * ga.x + a0.y * w.y * ga.y;
            const float2 a1 = m1[c];
            const float2 gb = g1[c];
            s1 += a1.x * w.x * gb.x + a1.y * w.y * gb.y;
        }

        // Warp reductions
        #pragma unroll
        for (int off = 16; off > 0; off >>= 1) {
            s0 += __shfl_xor_sync(0xffffffffu, s0, off);
            s1 += __shfl_xor_sync(0xffffffffu, s1, off);
        }

        if (lane == 0) {
            const float y0 = s0 + bias;
            const float y1 = s1 + bias;
            out[warp * N_DIM + n0]     = (1.0f / (1.0f + __expf(-y0)) - 0.5f) * scale;
            out[warp * N_DIM + n0 + 1] = (1.0f / (1.0f + __expf(-y1)) - 0.5f) * scale;
        }
        __syncthreads();   // protect gsh before next iteration overwrites it
    }
}

extern "C" void kernel_launch(void* const* d_in, const int* in_sizes, int n_in,
                              void* d_out, int out_size) {
    const float* x      = (const float*)d_in[0];
    const float* Wconv  = (const float*)d_in[1];
    const float* bconv  = (const float*)d_in[2];
    const float* mask   = (const float*)d_in[3];
    const int*   shifts = (const int*)d_in[4];
    float* out          = (float*)d_out;

    plaq_kernel<<<BLOCKS, THREADS>>>(x, Wconv, bconv, mask, shifts, out);
}

// round 12
// speedup vs baseline: 1.0949x; 1.0949x over previous
#include <cuda_runtime.h>
#include <math.h>

// Problem constants
#define O_DIM 32
#define I_DIM 32
#define K_DIM 13
#define N_DIM 4096
#define IK    (I_DIM * K_DIM)    // 416
#define WSIZE (O_DIM * IK)       // 13312 floats = 53 KB

#define THREADS 1024
#define BLOCKS  304              // 152 SMs * 2 resident blocks (all co-resident)

// Transposed x: xT[n][i] = x[i][n]  (4096 x 32 floats = 512 KB, L2-resident)
__device__ float xT[N_DIM * I_DIM];
// Grid-barrier epoch counter (monotonic across graph replays)
__device__ unsigned int g_bar;

__global__ void __launch_bounds__(THREADS, 2) plaq_kernel(
    const float* __restrict__ x,       // (I, N)
    const float* __restrict__ W,       // (O, I, K)
    const float* __restrict__ b,       // (O,)
    const float* __restrict__ mask,    // (N, O, I, K)
    const int*   __restrict__ shifts,  // (N, K)
    float*       __restrict__ out)     // (O, N)
{
    __shared__ float Wsh[WSIZE];
    __shared__ float gsh[2][2][IK];    // [buffer][which-n][e]

    const int tid  = threadIdx.x;
    const int warp = tid >> 5;   // warp == o in the dot phase
    const int lane = tid & 31;
    const int bid  = blockIdx.x;

    // ---- Phase 1: in-kernel transpose (blocks 0..127, one 32x32 tile each).
    // Tile buffer aliases the head of Wsh (Wsh is written only after this phase).
    {
        float (*tile)[33] = (float(*)[33])Wsh;
        if (bid < N_DIM / 32) {
            const int n0t = bid * 32;
            tile[warp][lane] = x[warp * N_DIM + n0t + lane];
            __syncthreads();
            xT[(n0t + warp) * I_DIM + lane] = tile[lane][warp];
            __threadfence();               // publish xT before arriving
        }
        __syncthreads();                   // tile reads done before Wsh overwrite
    }

    // ---- Phase 2: load W into shared (overlaps other blocks' transpose work)
    #pragma unroll
    for (int e = tid; e < WSIZE; e += THREADS)
        Wsh[e] = W[e];
    __syncthreads();

    // ---- Phase 3: software grid barrier (replay-safe epoch arithmetic)
    if (tid == 0) {
        const unsigned old    = atomicAdd(&g_bar, 1u);
        const unsigned target = (old / BLOCKS + 1u) * BLOCKS;
        while (atomicAdd(&g_bar, 0u) < target)
            __nanosleep(64);
    }
    __syncthreads();

    // Gather mapping: warps 0..25 own (which, k); one xT row per warp per group
    const bool gw    = (warp < 2 * K_DIM);
    const int  which = (warp >= K_DIM) ? 1 : 0;
    const int  gk    = warp - which * K_DIM;

    // Prime buffer 0 with group 0's gather
    {
        const int n0 = 2 * bid;
        if (gw) {
            const int s = shifts[(n0 + which) * K_DIM + gk];
            gsh[0][which][lane * K_DIM + gk] = xT[s * I_DIM + lane];
        }
        __syncthreads();
    }

    const float bias = b[warp];
    const float e_const = 2.718281828459045f;
    const float scale = (2.0f + 2.0f * e_const) / (e_const - 1.0f);
    const float* __restrict__ wrow = Wsh + warp * IK;

    // ---- Phase 4: main loop, two n's per iteration, ONE barrier each.
    // Gather for the NEXT group is issued AFTER the mask loads (never before:
    // R7/R10 showed front-issued gathers steal L1tex priority from the stream).
    int p = 0;
    for (int n0 = 2 * bid; n0 < N_DIM; n0 += 2 * BLOCKS) {
        // Dot: 26 coalesced scalar mask LDGs per warp (13 per n)
        const float* __restrict__ m0 = mask + ((size_t)n0 * O_DIM + warp) * IK;
        const float* __restrict__ m1 = m0 + O_DIM * IK;
        const float* __restrict__ g0 = gsh[p][0];
        const float* __restrict__ g1 = gsh[p][1];

        float s0 = 0.0f, s1 = 0.0f;
        #pragma unroll
        for (int j = 0; j < K_DIM; ++j) {
            const int e = j * 32 + lane;     // 13*32 == 416 exactly
            const float w = wrow[e];
            s0 += m0[e] * w * g0[e];
            s1 += m1[e] * w * g1[e];
        }

        // Compiler fence: keep the gather below from hoisting above the dot loads
        asm volatile("" ::: "memory");

        // Post-dot gather for the next group; latency hides under the
        // reduction + out-write + barrier straggler window.
        const int  n0n = n0 + 2 * BLOCKS;
        if (gw && (n0n < N_DIM)) {
            const int s = shifts[(n0n + which) * K_DIM + gk];
            gsh[p ^ 1][which][lane * K_DIM + gk] = xT[s * I_DIM + lane];
        }

        // Warp reductions
        #pragma unroll
        for (int off = 16; off > 0; off >>= 1) {
            s0 += __shfl_xor_sync(0xffffffffu, s0, off);
            s1 += __shfl_xor_sync(0xffffffffu, s1, off);
        }

        if (lane == 0) {
            const float y0 = s0 + bias;
            const float y1 = s1 + bias;
            out[warp * N_DIM + n0]     = (1.0f / (1.0f + __expf(-y0)) - 0.5f) * scale;
            out[warp * N_DIM + n0 + 1] = (1.0f / (1.0f + __expf(-y1)) - 0.5f) * scale;
        }

        __syncthreads();   // publishes gsh[p^1]; protects gsh[p] for next refill
        p ^= 1;
    }
}

extern "C" void kernel_launch(void* const* d_in, const int* in_sizes, int n_in,
                              void* d_out, int out_size) {
    const float* x      = (const float*)d_in[0];
    const float* Wconv  = (const float*)d_in[1];
    const float* bconv  = (const float*)d_in[2];
    const float* mask   = (const float*)d_in[3];
    const int*   shifts = (const int*)d_in[4];
    float* out          = (float*)d_out;

    plaq_kernel<<<BLOCKS, THREADS>>>(x, Wconv, bconv, mask, shifts, out);
}